// round 15
// baseline (speedup 1.0000x reference)
#include <cuda_runtime.h>
#include <cuda_bf16.h>
#include <math.h>
#include <stdint.h>

#define BB 8
#define LL 2048
#define DD 1024
#define HH 1024

// ---------------------------------------------------------------------------
// Scratch (bf16 split pairs + fp32 scores)
// ---------------------------------------------------------------------------
__device__ __nv_bfloat16 g_iq_h[BB * LL * DD], g_iq_l[BB * LL * DD];
__device__ __nv_bfloat16 g_ik_h[BB * LL * DD], g_ik_l[BB * LL * DD];
__device__ __nv_bfloat16 g_Wqt_h[HH * DD], g_Wqt_l[HH * DD];
__device__ __nv_bfloat16 g_Wkt_h[HH * DD], g_Wkt_l[HH * DD];
__device__ __nv_bfloat16 g_Q_h[BB * LL * HH], g_Q_l[BB * LL * HH];
__device__ __nv_bfloat16 g_K_h[BB * LL * HH], g_K_l[BB * LL * HH];
__device__ __nv_bfloat16 g_Vt_h[BB * DD * LL], g_Vt_l[BB * DD * LL];
__device__ __nv_bfloat16 g_P_h[(size_t)BB * LL * LL], g_P_l[(size_t)BB * LL * LL];
__device__ float g_S[(size_t)BB * LL * LL];

// ---------------------------------------------------------------------------
__device__ __forceinline__ uint32_t smem_u32(const void* p) {
    uint32_t a;
    asm("{ .reg .u64 t; cvta.to.shared.u64 t, %1; cvt.u32.u64 %0, t; }" : "=r"(a) : "l"(p));
    return a;
}

#define CP_ASYNC16(dst, src) \
    asm volatile("cp.async.cg.shared.global [%0], [%1], 16;" :: "r"(dst), "l"(src))
#define CP_COMMIT() asm volatile("cp.async.commit_group;" ::: "memory")
#define CP_WAIT(n)  asm volatile("cp.async.wait_group %0;" :: "n"(n) : "memory")

#define LDSM4(R, addr) \
    asm volatile("ldmatrix.sync.aligned.m8n8.x4.shared.b16 {%0,%1,%2,%3}, [%4];" \
        : "=r"((R)[0]), "=r"((R)[1]), "=r"((R)[2]), "=r"((R)[3]) : "r"(addr))

#define MMA16816(D, A, B0, B1) \
    asm volatile("mma.sync.aligned.m16n8k16.row.col.f32.bf16.bf16.f32 " \
        "{%0,%1,%2,%3},{%4,%5,%6,%7},{%8,%9},{%0,%1,%2,%3};" \
        : "+f"((D)[0]), "+f"((D)[1]), "+f"((D)[2]), "+f"((D)[3]) \
        : "r"((A)[0]), "r"((A)[1]), "r"((A)[2]), "r"((A)[3]), "r"(B0), "r"(B1))

__device__ __forceinline__ void split_val(float x, __nv_bfloat16& h, __nv_bfloat16& l) {
    h = __float2bfloat16(x);
    l = __float2bfloat16(x - __bfloat162float(h));
}

// ---------------------------------------------------------------------------
// bf16x3 NT GEMM (R13 winner, unchanged): CTA 128x128, BK=32, 3-stage
// cp.async pipeline, 8 warps (4m x 2n), warp tile 32x64, XOR-swizzled smem.
// ---------------------------------------------------------------------------
#define STAGE_SZ 32768
template <bool ADD_BIAS, bool SPLIT_OUT, bool DUAL>
__global__ __launch_bounds__(256, 2) void gemm_bf16x3(
    const __nv_bfloat16* __restrict__ Ah, const __nv_bfloat16* __restrict__ Al,
    const __nv_bfloat16* __restrict__ Bh, const __nv_bfloat16* __restrict__ Bl,
    const float* __restrict__ bias,
    float* __restrict__ Cf, __nv_bfloat16* __restrict__ Ch, __nv_bfloat16* __restrict__ Cl,
    int M, int N, int K, float alpha, size_t sA, size_t sB, size_t sC,
    const __nv_bfloat16* Ah2, const __nv_bfloat16* Al2,
    const __nv_bfloat16* Bh2, const __nv_bfloat16* Bl2,
    const float* bias2, __nv_bfloat16* Ch2, __nv_bfloat16* Cl2)
{
    extern __shared__ char smem[];
    const uint32_t sbase = smem_u32(smem);

    if (DUAL) {
        if (blockIdx.z == 1) {
            Ah = Ah2; Al = Al2; Bh = Bh2; Bl = Bl2;
            bias = bias2; Ch = Ch2; Cl = Cl2;
        }
    } else {
        Ah += (size_t)blockIdx.z * sA;  Al += (size_t)blockIdx.z * sA;
        Bh += (size_t)blockIdx.z * sB;  Bl += (size_t)blockIdx.z * sB;
        if (SPLIT_OUT) { Ch += (size_t)blockIdx.z * sC; Cl += (size_t)blockIdx.z * sC; }
        else           { Cf += (size_t)blockIdx.z * sC; }
    }

    const int t    = threadIdx.x;
    const int lane = t & 31;
    const int wid  = t >> 5;
    const int wm   = wid & 3;
    const int wn   = wid >> 2;
    const int rowBase = blockIdx.y * 128;
    const int colBase = blockIdx.x * 128;

    const int nIter = K >> 5;

    uint32_t aRow[2], aSw[2], bRow[4], bSw[4];
    const uint32_t cbA = (lane >> 4) & 1;
    const uint32_t cbB = (lane >> 3) & 1;
#pragma unroll
    for (int mt = 0; mt < 2; mt++) {
        uint32_t r = wm * 32 + mt * 16 + (lane & 7) + ((lane >> 3) & 1) * 8;
        aRow[mt] = r * 64;
        aSw[mt]  = (r >> 1) & 3;
    }
#pragma unroll
    for (int np = 0; np < 4; np++) {
        uint32_t r = wn * 64 + np * 16 + (lane & 7) + ((lane >> 4) & 1) * 8;
        bRow[np] = r * 64;
        bSw[np]  = (r >> 1) & 3;
    }

    const int pc = t & 3;

    auto produce = [&](int kt, int stg) {
        const uint32_t s0 = sbase + (uint32_t)stg * STAGE_SZ;
        const int k0 = kt << 5;
#pragma unroll
        for (int i = 0; i < 2; i++) {
            int r = (t >> 2) + i * 64;
            uint32_t sof = (uint32_t)(r * 64 + ((pc ^ ((r >> 1) & 3)) * 16));
            size_t ga = (size_t)(rowBase + r) * K + k0 + pc * 8;
            size_t gb = (size_t)(colBase + r) * K + k0 + pc * 8;
            CP_ASYNC16(s0 + sof,         Ah + ga);
            CP_ASYNC16(s0 + 8192 + sof,  Al + ga);
            CP_ASYNC16(s0 + 16384 + sof, Bh + gb);
            CP_ASYNC16(s0 + 24576 + sof, Bl + gb);
        }
        CP_COMMIT();
    };

    float acc[2][8][4];
#pragma unroll
    for (int i = 0; i < 2; i++)
#pragma unroll
        for (int j = 0; j < 8; j++)
#pragma unroll
            for (int v = 0; v < 4; v++) acc[i][j][v] = 0.0f;

    produce(0, 0);
    produce(1, 1);

    int stage = 0;
    for (int kt = 0; kt < nIter; kt++) {
        if (kt + 1 < nIter) { CP_WAIT(1); } else { CP_WAIT(0); }
        __syncthreads();
        if (kt + 2 < nIter) {
            int ps = stage + 2; if (ps >= 3) ps -= 3;
            produce(kt + 2, ps);
        }

        const uint32_t s0 = sbase + (uint32_t)stage * STAGE_SZ;

#pragma unroll
        for (int ks = 0; ks < 2; ks++) {
            const uint32_t chA = ks * 2 + cbA;
            const uint32_t chB = ks * 2 + cbB;
            uint32_t ah[2][4], al[2][4], bh[8][2];
#pragma unroll
            for (int mt = 0; mt < 2; mt++) {
                uint32_t ad = s0 + aRow[mt] + ((chA ^ aSw[mt]) << 4);
                LDSM4(ah[mt], ad);
                LDSM4(al[mt], ad + 8192);
            }
#pragma unroll
            for (int np = 0; np < 4; np++) {
                uint32_t bd = s0 + 16384 + bRow[np] + ((chB ^ bSw[np]) << 4);
                LDSM4(&bh[2 * np][0], bd);
            }
#pragma unroll
            for (int mt = 0; mt < 2; mt++)
#pragma unroll
                for (int nt = 0; nt < 8; nt++)
                    MMA16816(acc[mt][nt], ah[mt], bh[nt][0], bh[nt][1]);
#pragma unroll
            for (int mt = 0; mt < 2; mt++)
#pragma unroll
                for (int nt = 0; nt < 8; nt++)
                    MMA16816(acc[mt][nt], al[mt], bh[nt][0], bh[nt][1]);
            uint32_t bl[8][2];
#pragma unroll
            for (int np = 0; np < 4; np++) {
                uint32_t bd = s0 + 24576 + bRow[np] + ((chB ^ bSw[np]) << 4);
                LDSM4(&bl[2 * np][0], bd);
            }
#pragma unroll
            for (int mt = 0; mt < 2; mt++)
#pragma unroll
                for (int nt = 0; nt < 8; nt++)
                    MMA16816(acc[mt][nt], ah[mt], bl[nt][0], bl[nt][1]);
        }
        stage++; if (stage >= 3) stage = 0;
    }

    // Epilogue
#pragma unroll
    for (int mt = 0; mt < 2; mt++) {
#pragma unroll
        for (int nt = 0; nt < 8; nt++) {
            int row = rowBase + wm * 32 + mt * 16 + (lane >> 2);
            int col = colBase + wn * 64 + nt * 8 + 2 * (lane & 3);
            float v0 = acc[mt][nt][0] * alpha;
            float v1 = acc[mt][nt][1] * alpha;
            float v2 = acc[mt][nt][2] * alpha;
            float v3 = acc[mt][nt][3] * alpha;
            if (ADD_BIAS) {
                float b0 = bias[col], b1 = bias[col + 1];
                v0 += b0; v1 += b1; v2 += b0; v3 += b1;
            }
            if (SPLIT_OUT) {
                __nv_bfloat162 h01, l01, h23, l23;
                split_val(v0, h01.x, l01.x); split_val(v1, h01.y, l01.y);
                split_val(v2, h23.x, l23.x); split_val(v3, h23.y, l23.y);
                *(__nv_bfloat162*)(Ch + (size_t)row * N + col)       = h01;
                *(__nv_bfloat162*)(Cl + (size_t)row * N + col)       = l01;
                *(__nv_bfloat162*)(Ch + (size_t)(row + 8) * N + col) = h23;
                *(__nv_bfloat162*)(Cl + (size_t)(row + 8) * N + col) = l23;
            } else {
                *(float2*)(Cf + (size_t)row * N + col)       = make_float2(v0, v1);
                *(float2*)(Cf + (size_t)(row + 8) * N + col) = make_float2(v2, v3);
            }
        }
    }
}

// ---------------------------------------------------------------------------
// Merged prep kernel: block-range dispatch over
//   [0, 2*half)                : fp32->h/l split of in_q then in_k (4 elem/thr)
//   [2*half, +512)             : Wq, Wk 64x64 vectorized transpose+split
//   [2*half+512, +4096)        : in_k -> Vt 64x64 vectorized transpose+split
// ---------------------------------------------------------------------------
__device__ __forceinline__ void transpose64_split(
    const float* __restrict__ in, __nv_bfloat16* __restrict__ oh,
    __nv_bfloat16* __restrict__ ol, int R, int C, int r0, int c0)
{
    __shared__ float tile[64][65];
    const int t = threadIdx.x;
    // Load 64x64 floats: 1024 float4, 4 per thread
#pragma unroll
    for (int i = 0; i < 4; i++) {
        int lin = t + i * 256;          // 0..1023
        int r   = lin >> 4;             // 0..63
        int c4  = (lin & 15) * 4;
        float4 f = *(const float4*)(in + (size_t)(r0 + r) * C + c0 + c4);
        tile[r][c4 + 0] = f.x; tile[r][c4 + 1] = f.y;
        tile[r][c4 + 2] = f.z; tile[r][c4 + 3] = f.w;
    }
    __syncthreads();
    // Store transposed as bf16x2 pairs: out[c][r], pairs along r.
#pragma unroll
    for (int i = 0; i < 8; i++) {
        int lin  = t + i * 256;         // 0..2047
        int orow = lin >> 5;            // 0..63  (= input col)
        int opr  = (lin & 31) * 2;      // 0..62  (= input row pair)
        float x0 = tile[opr][orow];
        float x1 = tile[opr + 1][orow];
        __nv_bfloat162 h2, l2;
        split_val(x0, h2.x, l2.x);
        split_val(x1, h2.y, l2.y);
        size_t o = (size_t)(c0 + orow) * R + r0 + opr;
        *(__nv_bfloat162*)(oh + o) = h2;
        *(__nv_bfloat162*)(ol + o) = l2;
    }
}

__global__ __launch_bounds__(256) void prep_all(
    const float* __restrict__ in_q, __nv_bfloat16* __restrict__ iqh, __nv_bfloat16* __restrict__ iql,
    const float* __restrict__ in_k, __nv_bfloat16* __restrict__ ikh, __nv_bfloat16* __restrict__ ikl,
    const float* __restrict__ Wq, __nv_bfloat16* __restrict__ wqh, __nv_bfloat16* __restrict__ wql,
    const float* __restrict__ Wk, __nv_bfloat16* __restrict__ wkh, __nv_bfloat16* __restrict__ wkl,
    __nv_bfloat16* __restrict__ Vh, __nv_bfloat16* __restrict__ Vl,
    int half)
{
    int bx = blockIdx.x;
    if (bx < 2 * half) {
        const float* in; __nv_bfloat16 *h, *l;
        if (bx < half) { in = in_q; h = iqh; l = iql; }
        else           { in = in_k; h = ikh; l = ikl; bx -= half; }
        size_t i = ((size_t)bx * 256 + threadIdx.x) * 4;
        float4 v = *(const float4*)(in + i);
        __nv_bfloat162 h01, l01, h23, l23;
        split_val(v.x, h01.x, l01.x); split_val(v.y, h01.y, l01.y);
        split_val(v.z, h23.x, l23.x); split_val(v.w, h23.y, l23.y);
        *(__nv_bfloat162*)(h + i)     = h01;
        *(__nv_bfloat162*)(l + i)     = l01;
        *(__nv_bfloat162*)(h + i + 2) = h23;
        *(__nv_bfloat162*)(l + i + 2) = l23;
        return;
    }
    bx -= 2 * half;
    if (bx < 512) {
        // Weight transposes: 256 tiles each (16x16 of 64x64), R=C=1024
        const float* in; __nv_bfloat16 *oh, *ol;
        if (bx < 256) { in = Wq; oh = wqh; ol = wql; }
        else          { in = Wk; oh = wkh; ol = wkl; bx -= 256; }
        int r0 = (bx & 15) * 64;
        int c0 = (bx >> 4) * 64;
        transpose64_split(in, oh, ol, DD, HH, r0, c0);
        return;
    }
    bx -= 512;
    // Vt: per batch 32 r-tiles (L) x 16 c-tiles (D) = 512 tiles
    int b   = bx >> 9;
    int rem = bx & 511;
    int r0  = (rem & 31) * 64;       // along L (input rows)
    int c0  = (rem >> 5) * 64;       // along D (input cols)
    transpose64_split(in_k + (size_t)b * LL * DD,
                      Vh + (size_t)b * DD * LL,
                      Vl + (size_t)b * DD * LL,
                      LL, DD, r0, c0);
}

// ---------------------------------------------------------------------------
// Fused mask + softmax; 512 threads, warp-shuffle reductions (2 barriers).
// ---------------------------------------------------------------------------
__global__ __launch_bounds__(512) void softmax_mask(
    const float* __restrict__ S, const float* __restrict__ mask,
    __nv_bfloat16* __restrict__ Ph, __nv_bfloat16* __restrict__ Pl)
{
    const int row = blockIdx.x;
    const int b   = row >> 11;
    const int q   = row & (LL - 1);
    const float* mrow = mask + (size_t)b * LL;
    const float mq = (mrow[q] > 0.5f) ? 0.0f : -1.0e9f;
    const float* srow = S + (size_t)row * LL;

    const int t    = threadIdx.x;
    const int lane = t & 31;
    const int wrp  = t >> 5;
    const int idx  = t * 4;

    float4 f  = *(const float4*)(srow + idx);
    float4 mk = *(const float4*)(mrow + idx);
    float vals[4];
    {
        float a;
        a = ((mk.x > 0.5f) ? 0.0f : -1.0e9f) * mq; vals[0] = f.x + a;
        a = ((mk.y > 0.5f) ? 0.0f : -1.0e9f) * mq; vals[1] = f.y + a;
        a = ((mk.z > 0.5f) ? 0.0f : -1.0e9f) * mq; vals[2] = f.z + a;
        a = ((mk.w > 0.5f) ? 0.0f : -1.0e9f) * mq; vals[3] = f.w + a;
    }
    float lmax = fmaxf(fmaxf(vals[0], vals[1]), fmaxf(vals[2], vals[3]));
#pragma unroll
    for (int o = 16; o > 0; o >>= 1)
        lmax = fmaxf(lmax, __shfl_xor_sync(0xFFFFFFFFu, lmax, o));

    __shared__ float red[16];
    if (lane == 0) red[wrp] = lmax;
    __syncthreads();
    float rmax = red[0];
#pragma unroll
    for (int i = 1; i < 16; i++) rmax = fmaxf(rmax, red[i]);

    float lsum = 0.0f;
#pragma unroll
    for (int i = 0; i < 4; i++) {
        vals[i] = expf(vals[i] - rmax);
        lsum += vals[i];
    }
#pragma unroll
    for (int o = 16; o > 0; o >>= 1)
        lsum += __shfl_xor_sync(0xFFFFFFFFu, lsum, o);

    __shared__ float red2[16];
    if (lane == 0) red2[wrp] = lsum;
    __syncthreads();
    float rsum = 0.0f;
#pragma unroll
    for (int i = 0; i < 16; i++) rsum += red2[i];
    const float inv = 1.0f / rsum;

    float p0 = vals[0] * inv, p1 = vals[1] * inv;
    float p2 = vals[2] * inv, p3 = vals[3] * inv;
    __nv_bfloat162 h01, l01, h23, l23;
    split_val(p0, h01.x, l01.x); split_val(p1, h01.y, l01.y);
    split_val(p2, h23.x, l23.x); split_val(p3, h23.y, l23.y);
    size_t o = (size_t)row * LL + idx;
    *(__nv_bfloat162*)(Ph + o)     = h01;
    *(__nv_bfloat162*)(Pl + o)     = l01;
    *(__nv_bfloat162*)(Ph + o + 2) = h23;
    *(__nv_bfloat162*)(Pl + o + 2) = l23;
}

// ---------------------------------------------------------------------------
extern "C" void kernel_launch(void* const* d_in, const int* in_sizes, int n_in,
                              void* d_out, int out_size)
{
    const float* in_q  = (const float*)d_in[0];
    const float* in_k  = (const float*)d_in[1];
    const float* kmask = (const float*)d_in[2];
    const float* Wq    = (const float*)d_in[3];
    const float* bq    = (const float*)d_in[4];
    const float* Wk    = (const float*)d_in[5];
    const float* bk    = (const float*)d_in[6];
    float* out = (float*)d_out;

    __nv_bfloat16 *iqh, *iql, *ikh, *ikl, *wqh, *wql, *wkh, *wkl;
    __nv_bfloat16 *Qh, *Ql, *Kh, *Kl, *Vh, *Vl, *Ph, *Pl;
    float* Sp;
    cudaGetSymbolAddress((void**)&iqh, g_iq_h);  cudaGetSymbolAddress((void**)&iql, g_iq_l);
    cudaGetSymbolAddress((void**)&ikh, g_ik_h);  cudaGetSymbolAddress((void**)&ikl, g_ik_l);
    cudaGetSymbolAddress((void**)&wqh, g_Wqt_h); cudaGetSymbolAddress((void**)&wql, g_Wqt_l);
    cudaGetSymbolAddress((void**)&wkh, g_Wkt_h); cudaGetSymbolAddress((void**)&wkl, g_Wkt_l);
    cudaGetSymbolAddress((void**)&Qh,  g_Q_h);   cudaGetSymbolAddress((void**)&Ql,  g_Q_l);
    cudaGetSymbolAddress((void**)&Kh,  g_K_h);   cudaGetSymbolAddress((void**)&Kl,  g_K_l);
    cudaGetSymbolAddress((void**)&Vh,  g_Vt_h);  cudaGetSymbolAddress((void**)&Vl,  g_Vt_l);
    cudaGetSymbolAddress((void**)&Ph,  g_P_h);   cudaGetSymbolAddress((void**)&Pl,  g_P_l);
    cudaGetSymbolAddress((void**)&Sp,  g_S);

    const int SMEM_BYTES = 3 * STAGE_SZ;   // 98304
    cudaFuncSetAttribute(gemm_bf16x3<true, true, true>,
                         cudaFuncAttributeMaxDynamicSharedMemorySize, SMEM_BYTES);
    cudaFuncSetAttribute(gemm_bf16x3<false, false, false>,
                         cudaFuncAttributeMaxDynamicSharedMemorySize, SMEM_BYTES);

    // 0) All prep in ONE launch: splits + weight transposes + Vt transpose
    {
        int half = BB * LL * DD / 1024;        // 16384
        int grid = 2 * half + 512 + 4096;      // 37376
        prep_all<<<grid, 256>>>(in_q, iqh, iql, in_k, ikh, ikl,
                                Wq, wqh, wql, Wk, wkh, wkl, Vh, Vl, half);
    }

    // 1) Both projections in ONE launch (z=0: Q-set, z=1: K-set)
    {
        dim3 grid(HH / 128, (BB * LL) / 128, 2);
        gemm_bf16x3<true, true, true><<<grid, 256, SMEM_BYTES>>>(
            iqh, iql, wqh, wql, bq, nullptr, Qh, Ql,
            BB * LL, HH, DD, 1.0f, 0, 0, 0,
            ikh, ikl, wkh, wkl, bk, Kh, Kl);
    }

    // 2) Scores: S[b] = (Q[b] @ K[b]^T) / 32
    {
        dim3 grid(LL / 128, LL / 128, BB);
        gemm_bf16x3<false, false, false><<<grid, 256, SMEM_BYTES>>>(
            Qh, Ql, Kh, Kl, nullptr, Sp, nullptr, nullptr,
            LL, LL, HH, 0.03125f,
            (size_t)LL * HH, (size_t)LL * HH, (size_t)LL * LL,
            nullptr, nullptr, nullptr, nullptr, nullptr, nullptr, nullptr);
    }

    // 3) Masked softmax -> split P
    softmax_mask<<<BB * LL, 512>>>(Sp, kmask, Ph, Pl);

    // 4) Output: out[b] = P[b] @ in_k[b]  (NT with Vt)
    {
        dim3 grid(DD / 128, LL / 128, BB);
        gemm_bf16x3<false, false, false><<<grid, 256, SMEM_BYTES>>>(
            Ph, Pl, Vh, Vl, nullptr, out, nullptr, nullptr,
            LL, DD, LL, 1.0f,
            (size_t)LL * LL, (size_t)DD * LL, (size_t)LL * DD,
            nullptr, nullptr, nullptr, nullptr, nullptr, nullptr, nullptr);
    }
}

// round 16
// speedup vs baseline: 1.5384x; 1.5384x over previous
#include <cuda_runtime.h>
#include <cuda_bf16.h>
#include <math.h>
#include <stdint.h>

#define BB 8
#define LL 2048
#define DD 1024
#define HH 1024

// ---------------------------------------------------------------------------
// Scratch (bf16 split pairs + fp32 scores)
// ---------------------------------------------------------------------------
__device__ __nv_bfloat16 g_iq_h[BB * LL * DD], g_iq_l[BB * LL * DD];
__device__ __nv_bfloat16 g_ik_h[BB * LL * DD], g_ik_l[BB * LL * DD];
__device__ __nv_bfloat16 g_Wqt_h[HH * DD], g_Wqt_l[HH * DD];
__device__ __nv_bfloat16 g_Wkt_h[HH * DD], g_Wkt_l[HH * DD];
__device__ __nv_bfloat16 g_Q_h[BB * LL * HH], g_Q_l[BB * LL * HH];
__device__ __nv_bfloat16 g_K_h[BB * LL * HH], g_K_l[BB * LL * HH];
__device__ __nv_bfloat16 g_Vt_h[BB * DD * LL], g_Vt_l[BB * DD * LL];
__device__ __nv_bfloat16 g_P_h[(size_t)BB * LL * LL], g_P_l[(size_t)BB * LL * LL];
__device__ float g_S[(size_t)BB * LL * LL];

// ---------------------------------------------------------------------------
__device__ __forceinline__ uint32_t smem_u32(const void* p) {
    uint32_t a;
    asm("{ .reg .u64 t; cvta.to.shared.u64 t, %1; cvt.u32.u64 %0, t; }" : "=r"(a) : "l"(p));
    return a;
}

#define CP_ASYNC16(dst, src) \
    asm volatile("cp.async.cg.shared.global [%0], [%1], 16;" :: "r"(dst), "l"(src))
#define CP_COMMIT() asm volatile("cp.async.commit_group;" ::: "memory")
#define CP_WAIT(n)  asm volatile("cp.async.wait_group %0;" :: "n"(n) : "memory")

#define LDSM4(R, addr) \
    asm volatile("ldmatrix.sync.aligned.m8n8.x4.shared.b16 {%0,%1,%2,%3}, [%4];" \
        : "=r"((R)[0]), "=r"((R)[1]), "=r"((R)[2]), "=r"((R)[3]) : "r"(addr))

#define MMA16816(D, A, B0, B1) \
    asm volatile("mma.sync.aligned.m16n8k16.row.col.f32.bf16.bf16.f32 " \
        "{%0,%1,%2,%3},{%4,%5,%6,%7},{%8,%9},{%0,%1,%2,%3};" \
        : "+f"((D)[0]), "+f"((D)[1]), "+f"((D)[2]), "+f"((D)[3]) \
        : "r"((A)[0]), "r"((A)[1]), "r"((A)[2]), "r"((A)[3]), "r"(B0), "r"(B1))

__device__ __forceinline__ void split_val(float x, __nv_bfloat16& h, __nv_bfloat16& l) {
    h = __float2bfloat16(x);
    l = __float2bfloat16(x - __bfloat162float(h));
}

// ---------------------------------------------------------------------------
// bf16x3 NT GEMM (R13 winner, unchanged): CTA 128x128, BK=32, 3-stage
// cp.async pipeline, 8 warps (4m x 2n), warp tile 32x64, XOR-swizzled smem.
// ---------------------------------------------------------------------------
#define STAGE_SZ 32768
template <bool ADD_BIAS, bool SPLIT_OUT, bool DUAL>
__global__ __launch_bounds__(256, 2) void gemm_bf16x3(
    const __nv_bfloat16* __restrict__ Ah, const __nv_bfloat16* __restrict__ Al,
    const __nv_bfloat16* __restrict__ Bh, const __nv_bfloat16* __restrict__ Bl,
    const float* __restrict__ bias,
    float* __restrict__ Cf, __nv_bfloat16* __restrict__ Ch, __nv_bfloat16* __restrict__ Cl,
    int M, int N, int K, float alpha, size_t sA, size_t sB, size_t sC,
    const __nv_bfloat16* Ah2, const __nv_bfloat16* Al2,
    const __nv_bfloat16* Bh2, const __nv_bfloat16* Bl2,
    const float* bias2, __nv_bfloat16* Ch2, __nv_bfloat16* Cl2)
{
    extern __shared__ char smem[];
    const uint32_t sbase = smem_u32(smem);

    if (DUAL) {
        if (blockIdx.z == 1) {
            Ah = Ah2; Al = Al2; Bh = Bh2; Bl = Bl2;
            bias = bias2; Ch = Ch2; Cl = Cl2;
        }
    } else {
        Ah += (size_t)blockIdx.z * sA;  Al += (size_t)blockIdx.z * sA;
        Bh += (size_t)blockIdx.z * sB;  Bl += (size_t)blockIdx.z * sB;
        if (SPLIT_OUT) { Ch += (size_t)blockIdx.z * sC; Cl += (size_t)blockIdx.z * sC; }
        else           { Cf += (size_t)blockIdx.z * sC; }
    }

    const int t    = threadIdx.x;
    const int lane = t & 31;
    const int wid  = t >> 5;
    const int wm   = wid & 3;
    const int wn   = wid >> 2;
    const int rowBase = blockIdx.y * 128;
    const int colBase = blockIdx.x * 128;

    const int nIter = K >> 5;

    uint32_t aRow[2], aSw[2], bRow[4], bSw[4];
    const uint32_t cbA = (lane >> 4) & 1;
    const uint32_t cbB = (lane >> 3) & 1;
#pragma unroll
    for (int mt = 0; mt < 2; mt++) {
        uint32_t r = wm * 32 + mt * 16 + (lane & 7) + ((lane >> 3) & 1) * 8;
        aRow[mt] = r * 64;
        aSw[mt]  = (r >> 1) & 3;
    }
#pragma unroll
    for (int np = 0; np < 4; np++) {
        uint32_t r = wn * 64 + np * 16 + (lane & 7) + ((lane >> 4) & 1) * 8;
        bRow[np] = r * 64;
        bSw[np]  = (r >> 1) & 3;
    }

    const int pc = t & 3;

    auto produce = [&](int kt, int stg) {
        const uint32_t s0 = sbase + (uint32_t)stg * STAGE_SZ;
        const int k0 = kt << 5;
#pragma unroll
        for (int i = 0; i < 2; i++) {
            int r = (t >> 2) + i * 64;
            uint32_t sof = (uint32_t)(r * 64 + ((pc ^ ((r >> 1) & 3)) * 16));
            size_t ga = (size_t)(rowBase + r) * K + k0 + pc * 8;
            size_t gb = (size_t)(colBase + r) * K + k0 + pc * 8;
            CP_ASYNC16(s0 + sof,         Ah + ga);
            CP_ASYNC16(s0 + 8192 + sof,  Al + ga);
            CP_ASYNC16(s0 + 16384 + sof, Bh + gb);
            CP_ASYNC16(s0 + 24576 + sof, Bl + gb);
        }
        CP_COMMIT();
    };

    float acc[2][8][4];
#pragma unroll
    for (int i = 0; i < 2; i++)
#pragma unroll
        for (int j = 0; j < 8; j++)
#pragma unroll
            for (int v = 0; v < 4; v++) acc[i][j][v] = 0.0f;

    produce(0, 0);
    produce(1, 1);

    int stage = 0;
    for (int kt = 0; kt < nIter; kt++) {
        if (kt + 1 < nIter) { CP_WAIT(1); } else { CP_WAIT(0); }
        __syncthreads();
        if (kt + 2 < nIter) {
            int ps = stage + 2; if (ps >= 3) ps -= 3;
            produce(kt + 2, ps);
        }

        const uint32_t s0 = sbase + (uint32_t)stage * STAGE_SZ;

#pragma unroll
        for (int ks = 0; ks < 2; ks++) {
            const uint32_t chA = ks * 2 + cbA;
            const uint32_t chB = ks * 2 + cbB;
            uint32_t ah[2][4], al[2][4], bh[8][2];
#pragma unroll
            for (int mt = 0; mt < 2; mt++) {
                uint32_t ad = s0 + aRow[mt] + ((chA ^ aSw[mt]) << 4);
                LDSM4(ah[mt], ad);
                LDSM4(al[mt], ad + 8192);
            }
#pragma unroll
            for (int np = 0; np < 4; np++) {
                uint32_t bd = s0 + 16384 + bRow[np] + ((chB ^ bSw[np]) << 4);
                LDSM4(&bh[2 * np][0], bd);
            }
#pragma unroll
            for (int mt = 0; mt < 2; mt++)
#pragma unroll
                for (int nt = 0; nt < 8; nt++)
                    MMA16816(acc[mt][nt], ah[mt], bh[nt][0], bh[nt][1]);
#pragma unroll
            for (int mt = 0; mt < 2; mt++)
#pragma unroll
                for (int nt = 0; nt < 8; nt++)
                    MMA16816(acc[mt][nt], al[mt], bh[nt][0], bh[nt][1]);
            uint32_t bl[8][2];
#pragma unroll
            for (int np = 0; np < 4; np++) {
                uint32_t bd = s0 + 24576 + bRow[np] + ((chB ^ bSw[np]) << 4);
                LDSM4(&bl[2 * np][0], bd);
            }
#pragma unroll
            for (int mt = 0; mt < 2; mt++)
#pragma unroll
                for (int nt = 0; nt < 8; nt++)
                    MMA16816(acc[mt][nt], ah[mt], bl[nt][0], bl[nt][1]);
        }
        stage++; if (stage >= 3) stage = 0;
    }

    // Epilogue
#pragma unroll
    for (int mt = 0; mt < 2; mt++) {
#pragma unroll
        for (int nt = 0; nt < 8; nt++) {
            int row = rowBase + wm * 32 + mt * 16 + (lane >> 2);
            int col = colBase + wn * 64 + nt * 8 + 2 * (lane & 3);
            float v0 = acc[mt][nt][0] * alpha;
            float v1 = acc[mt][nt][1] * alpha;
            float v2 = acc[mt][nt][2] * alpha;
            float v3 = acc[mt][nt][3] * alpha;
            if (ADD_BIAS) {
                float b0 = bias[col], b1 = bias[col + 1];
                v0 += b0; v1 += b1; v2 += b0; v3 += b1;
            }
            if (SPLIT_OUT) {
                __nv_bfloat162 h01, l01, h23, l23;
                split_val(v0, h01.x, l01.x); split_val(v1, h01.y, l01.y);
                split_val(v2, h23.x, l23.x); split_val(v3, h23.y, l23.y);
                *(__nv_bfloat162*)(Ch + (size_t)row * N + col)       = h01;
                *(__nv_bfloat162*)(Cl + (size_t)row * N + col)       = l01;
                *(__nv_bfloat162*)(Ch + (size_t)(row + 8) * N + col) = h23;
                *(__nv_bfloat162*)(Cl + (size_t)(row + 8) * N + col) = l23;
            } else {
                *(float2*)(Cf + (size_t)row * N + col)       = make_float2(v0, v1);
                *(float2*)(Cf + (size_t)(row + 8) * N + col) = make_float2(v2, v3);
            }
        }
    }
}

// ---------------------------------------------------------------------------
// Merged prep kernel (R15): splits + weight transposes + Vt transpose.
// ---------------------------------------------------------------------------
__device__ __forceinline__ void transpose64_split(
    const float* __restrict__ in, __nv_bfloat16* __restrict__ oh,
    __nv_bfloat16* __restrict__ ol, int R, int C, int r0, int c0)
{
    __shared__ float tile[64][65];
    const int t = threadIdx.x;
#pragma unroll
    for (int i = 0; i < 4; i++) {
        int lin = t + i * 256;
        int r   = lin >> 4;
        int c4  = (lin & 15) * 4;
        float4 f = *(const float4*)(in + (size_t)(r0 + r) * C + c0 + c4);
        tile[r][c4 + 0] = f.x; tile[r][c4 + 1] = f.y;
        tile[r][c4 + 2] = f.z; tile[r][c4 + 3] = f.w;
    }
    __syncthreads();
#pragma unroll
    for (int i = 0; i < 8; i++) {
        int lin  = t + i * 256;
        int orow = lin >> 5;
        int opr  = (lin & 31) * 2;
        float x0 = tile[opr][orow];
        float x1 = tile[opr + 1][orow];
        __nv_bfloat162 h2, l2;
        split_val(x0, h2.x, l2.x);
        split_val(x1, h2.y, l2.y);
        size_t o = (size_t)(c0 + orow) * R + r0 + opr;
        *(__nv_bfloat162*)(oh + o) = h2;
        *(__nv_bfloat162*)(ol + o) = l2;
    }
}

__global__ __launch_bounds__(256) void prep_all(
    const float* __restrict__ in_q, __nv_bfloat16* __restrict__ iqh, __nv_bfloat16* __restrict__ iql,
    const float* __restrict__ in_k, __nv_bfloat16* __restrict__ ikh, __nv_bfloat16* __restrict__ ikl,
    const float* __restrict__ Wq, __nv_bfloat16* __restrict__ wqh, __nv_bfloat16* __restrict__ wql,
    const float* __restrict__ Wk, __nv_bfloat16* __restrict__ wkh, __nv_bfloat16* __restrict__ wkl,
    __nv_bfloat16* __restrict__ Vh, __nv_bfloat16* __restrict__ Vl,
    int half)
{
    int bx = blockIdx.x;
    if (bx < 2 * half) {
        const float* in; __nv_bfloat16 *h, *l;
        if (bx < half) { in = in_q; h = iqh; l = iql; }
        else           { in = in_k; h = ikh; l = ikl; bx -= half; }
        size_t i = ((size_t)bx * 256 + threadIdx.x) * 4;
        float4 v = *(const float4*)(in + i);
        __nv_bfloat162 h01, l01, h23, l23;
        split_val(v.x, h01.x, l01.x); split_val(v.y, h01.y, l01.y);
        split_val(v.z, h23.x, l23.x); split_val(v.w, h23.y, l23.y);
        *(__nv_bfloat162*)(h + i)     = h01;
        *(__nv_bfloat162*)(l + i)     = l01;
        *(__nv_bfloat162*)(h + i + 2) = h23;
        *(__nv_bfloat162*)(l + i + 2) = l23;
        return;
    }
    bx -= 2 * half;
    if (bx < 512) {
        const float* in; __nv_bfloat16 *oh, *ol;
        if (bx < 256) { in = Wq; oh = wqh; ol = wql; }
        else          { in = Wk; oh = wkh; ol = wkl; bx -= 256; }
        int r0 = (bx & 15) * 64;
        int c0 = (bx >> 4) * 64;
        transpose64_split(in, oh, ol, DD, HH, r0, c0);
        return;
    }
    bx -= 512;
    int b   = bx >> 9;
    int rem = bx & 511;
    int r0  = (rem & 31) * 64;
    int c0  = (rem >> 5) * 64;
    transpose64_split(in_k + (size_t)b * LL * DD,
                      Vh + (size_t)b * DD * LL,
                      Vl + (size_t)b * DD * LL,
                      LL, DD, r0, c0);
}

// ---------------------------------------------------------------------------
// Fused mask + softmax; 512 threads. __expf + shuffle-tree cross-warp reduce.
// ---------------------------------------------------------------------------
__global__ __launch_bounds__(512) void softmax_mask(
    const float* __restrict__ S, const float* __restrict__ mask,
    __nv_bfloat16* __restrict__ Ph, __nv_bfloat16* __restrict__ Pl)
{
    const int row = blockIdx.x;
    const int b   = row >> 11;
    const int q   = row & (LL - 1);
    const float* mrow = mask + (size_t)b * LL;
    const float mq = (mrow[q] > 0.5f) ? 0.0f : -1.0e9f;
    const float* srow = S + (size_t)row * LL;

    const int t    = threadIdx.x;
    const int lane = t & 31;
    const int wrp  = t >> 5;
    const int idx  = t * 4;

    float4 f  = *(const float4*)(srow + idx);
    float4 mk = *(const float4*)(mrow + idx);
    float vals[4];
    {
        float a;
        a = ((mk.x > 0.5f) ? 0.0f : -1.0e9f) * mq; vals[0] = f.x + a;
        a = ((mk.y > 0.5f) ? 0.0f : -1.0e9f) * mq; vals[1] = f.y + a;
        a = ((mk.z > 0.5f) ? 0.0f : -1.0e9f) * mq; vals[2] = f.z + a;
        a = ((mk.w > 0.5f) ? 0.0f : -1.0e9f) * mq; vals[3] = f.w + a;
    }
    float lmax = fmaxf(fmaxf(vals[0], vals[1]), fmaxf(vals[2], vals[3]));
#pragma unroll
    for (int o = 16; o > 0; o >>= 1)
        lmax = fmaxf(lmax, __shfl_xor_sync(0xFFFFFFFFu, lmax, o));

    __shared__ float red[16];
    __shared__ float bcast[2];
    if (lane == 0) red[wrp] = lmax;
    __syncthreads();
    if (wrp == 0) {
        float v = red[lane & 15];
#pragma unroll
        for (int o = 8; o > 0; o >>= 1)
            v = fmaxf(v, __shfl_xor_sync(0xFFFFFFFFu, v, o));
        if (lane == 0) bcast[0] = v;
    }
    __syncthreads();
    const float rmax = bcast[0];

    float lsum = 0.0f;
#pragma unroll
    for (int i = 0; i < 4; i++) {
        vals[i] = __expf(vals[i] - rmax);
        lsum += vals[i];
    }
#pragma unroll
    for (int o = 16; o > 0; o >>= 1)
        lsum += __shfl_xor_sync(0xFFFFFFFFu, lsum, o);

    if (lane == 0) red[wrp] = lsum;
    __syncthreads();
    if (wrp == 0) {
        float v = red[lane & 15];
#pragma unroll
        for (int o = 8; o > 0; o >>= 1)
            v += __shfl_xor_sync(0xFFFFFFFFu, v, o);
        if (lane == 0) bcast[1] = v;
    }
    __syncthreads();
    const float inv = 1.0f / bcast[1];

    float p0 = vals[0] * inv, p1 = vals[1] * inv;
    float p2 = vals[2] * inv, p3 = vals[3] * inv;
    __nv_bfloat162 h01, l01, h23, l23;
    split_val(p0, h01.x, l01.x); split_val(p1, h01.y, l01.y);
    split_val(p2, h23.x, l23.x); split_val(p3, h23.y, l23.y);
    size_t o = (size_t)row * LL + idx;
    *(__nv_bfloat162*)(Ph + o)     = h01;
    *(__nv_bfloat162*)(Pl + o)     = l01;
    *(__nv_bfloat162*)(Ph + o + 2) = h23;
    *(__nv_bfloat162*)(Pl + o + 2) = l23;
}

// ---------------------------------------------------------------------------
extern "C" void kernel_launch(void* const* d_in, const int* in_sizes, int n_in,
                              void* d_out, int out_size)
{
    const float* in_q  = (const float*)d_in[0];
    const float* in_k  = (const float*)d_in[1];
    const float* kmask = (const float*)d_in[2];
    const float* Wq    = (const float*)d_in[3];
    const float* bq    = (const float*)d_in[4];
    const float* Wk    = (const float*)d_in[5];
    const float* bk    = (const float*)d_in[6];
    float* out = (float*)d_out;

    __nv_bfloat16 *iqh, *iql, *ikh, *ikl, *wqh, *wql, *wkh, *wkl;
    __nv_bfloat16 *Qh, *Ql, *Kh, *Kl, *Vh, *Vl, *Ph, *Pl;
    float* Sp;
    cudaGetSymbolAddress((void**)&iqh, g_iq_h);  cudaGetSymbolAddress((void**)&iql, g_iq_l);
    cudaGetSymbolAddress((void**)&ikh, g_ik_h);  cudaGetSymbolAddress((void**)&ikl, g_ik_l);
    cudaGetSymbolAddress((void**)&wqh, g_Wqt_h); cudaGetSymbolAddress((void**)&wql, g_Wqt_l);
    cudaGetSymbolAddress((void**)&wkh, g_Wkt_h); cudaGetSymbolAddress((void**)&wkl, g_Wkt_l);
    cudaGetSymbolAddress((void**)&Qh,  g_Q_h);   cudaGetSymbolAddress((void**)&Ql,  g_Q_l);
    cudaGetSymbolAddress((void**)&Kh,  g_K_h);   cudaGetSymbolAddress((void**)&Kl,  g_K_l);
    cudaGetSymbolAddress((void**)&Vh,  g_Vt_h);  cudaGetSymbolAddress((void**)&Vl,  g_Vt_l);
    cudaGetSymbolAddress((void**)&Ph,  g_P_h);   cudaGetSymbolAddress((void**)&Pl,  g_P_l);
    cudaGetSymbolAddress((void**)&Sp,  g_S);

    const int SMEM_BYTES = 3 * STAGE_SZ;   // 98304
    cudaFuncSetAttribute(gemm_bf16x3<true, true, true>,
                         cudaFuncAttributeMaxDynamicSharedMemorySize, SMEM_BYTES);
    cudaFuncSetAttribute(gemm_bf16x3<false, false, false>,
                         cudaFuncAttributeMaxDynamicSharedMemorySize, SMEM_BYTES);

    // 0) All prep in ONE launch
    {
        int half = BB * LL * DD / 1024;        // 16384
        int grid = 2 * half + 512 + 4096;      // 37376
        prep_all<<<grid, 256>>>(in_q, iqh, iql, in_k, ikh, ikl,
                                Wq, wqh, wql, Wk, wkh, wkl, Vh, Vl, half);
    }

    // 1) Both projections in ONE launch (z=0: Q-set, z=1: K-set)
    {
        dim3 grid(HH / 128, (BB * LL) / 128, 2);
        gemm_bf16x3<true, true, true><<<grid, 256, SMEM_BYTES>>>(
            iqh, iql, wqh, wql, bq, nullptr, Qh, Ql,
            BB * LL, HH, DD, 1.0f, 0, 0, 0,
            ikh, ikl, wkh, wkl, bk, Kh, Kl);
    }

    // 2) Scores: S[b] = (Q[b] @ K[b]^T) / 32
    {
        dim3 grid(LL / 128, LL / 128, BB);
        gemm_bf16x3<false, false, false><<<grid, 256, SMEM_BYTES>>>(
            Qh, Ql, Kh, Kl, nullptr, Sp, nullptr, nullptr,
            LL, LL, HH, 0.03125f,
            (size_t)LL * HH, (size_t)LL * HH, (size_t)LL * LL,
            nullptr, nullptr, nullptr, nullptr, nullptr, nullptr, nullptr);
    }

    // 3) Masked softmax -> split P
    softmax_mask<<<BB * LL, 512>>>(Sp, kmask, Ph, Pl);

    // 4) Output: out[b] = P[b] @ in_k[b]  (NT with Vt)
    {
        dim3 grid(DD / 128, LL / 128, BB);
        gemm_bf16x3<false, false, false><<<grid, 256, SMEM_BYTES>>>(
            Ph, Pl, Vh, Vl, nullptr, out, nullptr, nullptr,
            LL, DD, LL, 1.0f,
            (size_t)LL * LL, (size_t)DD * LL, (size_t)LL * DD,
            nullptr, nullptr, nullptr, nullptr, nullptr, nullptr, nullptr);
    }
}